// round 13
// baseline (speedup 1.0000x reference)
#include <cuda_runtime.h>
#include <cuda_fp16.h>

#define USER_NUM 100000
#define ITEM_NUM 50000
#define N_NODES  150000
#define HD       64
#define N_EDGES  4000000
#define SCAN_BLK 1024
#define SCAN_NB  ((N_NODES + SCAN_BLK - 1) / SCAN_BLK)   // 147

// ---- scratch (no allocation allowed -> __device__ globals) ----
// Globals start zeroed; the final layer's epilogue re-zeroes the degree
// counters so every (graph-replayed) call sees identical initial state.
__device__ int           d_deg_out[N_NODES];
__device__ int           d_deg_in[N_NODES];
__device__ int           d_blocksum[SCAN_NB];
__device__ int           d_ptr[N_NODES + 1];
__device__ unsigned char d_rank[N_EDGES];     // edge rank in dst bucket (max deg ~60 << 256)
__device__ int           d_esrc[N_EDGES];     // raw src index (CSR by dst)
__device__ float         d_onorm[N_NODES];    // odeg^-1/2
__device__ float         d_oinv[N_NODES];     // odeg^+1/2 (undo pre-scale)
__device__ float         d_inorm[N_NODES];    // ideg^-1/2
__device__ __half2       d_gA[N_NODES * 32];  // g0  (row = 64 half = 8 int4)
__device__ __half2       d_gB[N_NODES * 32];  // g1
__device__ __half2       d_gC[N_NODES * 32];  // g2

// 1) degree histograms; in-degree atomic's return = edge's bucket rank (u8-packed)
__global__ void k_hist(const int4* __restrict__ src4, const int4* __restrict__ dst4) {
    int i = blockIdx.x * blockDim.x + threadIdx.x;
    if (i >= N_EDGES / 4) return;
    int4 s = src4[i];
    int4 d = dst4[i];
    atomicAdd(&d_deg_out[s.x], 1); atomicAdd(&d_deg_out[s.y], 1);
    atomicAdd(&d_deg_out[s.z], 1); atomicAdd(&d_deg_out[s.w], 1);
    uchar4 r;
    r.x = (unsigned char)atomicAdd(&d_deg_in[d.x], 1);
    r.y = (unsigned char)atomicAdd(&d_deg_in[d.y], 1);
    r.z = (unsigned char)atomicAdd(&d_deg_in[d.z], 1);
    r.w = (unsigned char)atomicAdd(&d_deg_in[d.w], 1);
    ((uchar4*)d_rank)[i] = r;
}

// 2a) per-block sums of in-degree
__global__ void k_scanA() {
    __shared__ int sh[SCAN_BLK];
    int t = threadIdx.x;
    int i = blockIdx.x * SCAN_BLK + t;
    sh[t] = (i < N_NODES) ? d_deg_in[i] : 0;
    __syncthreads();
    for (int off = SCAN_BLK / 2; off > 0; off >>= 1) {
        if (t < off) sh[t] += sh[t + off];
        __syncthreads();
    }
    if (t == 0) d_blocksum[blockIdx.x] = sh[0];
}

// 2b+c) fused: per-block global offset from the 147 block sums, then
//        block-local exclusive scan -> ptr
__global__ void k_scanC() {
    __shared__ int sh[SCAN_BLK];
    __shared__ int bs[256];
    int t = threadIdx.x;
    bs[t & 255] = 0;
    __syncthreads();
    if (t < SCAN_NB) bs[t] = d_blocksum[t];
    __syncthreads();
    if (t == 0) {
        int run = 0;
        for (int b = 0; b < SCAN_NB; b++) { int v = bs[b]; bs[b] = run; run += v; }
    }
    __syncthreads();
    int blockoff = bs[blockIdx.x];

    int i = blockIdx.x * SCAN_BLK + t;
    int ideg = (i < N_NODES) ? d_deg_in[i] : 0;
    sh[t] = ideg;
    __syncthreads();
    for (int off = 1; off < SCAN_BLK; off <<= 1) {
        int v = sh[t];
        if (t >= off) v += sh[t - off];
        __syncthreads();
        sh[t] = v;
        __syncthreads();
    }
    if (i < N_NODES) {
        int excl = sh[t] - ideg + blockoff;
        d_ptr[i] = excl;
        if (i == N_NODES - 1) d_ptr[N_NODES] = excl + ideg;
    }
}

// 3) MERGED scatter + init (profiled 4th launch).
__global__ void k_scatter_init(const int4* __restrict__ src4,
                               const int4* __restrict__ dst4,
                               const float* __restrict__ user,
                               const float* __restrict__ item) {
    int i = blockIdx.x * blockDim.x + threadIdx.x;

    if (i < N_EDGES / 4) {
        int4 s = src4[i];
        int4 d = dst4[i];
        uchar4 r = ((const uchar4*)d_rank)[i];
        d_esrc[d_ptr[d.x] + r.x] = s.x;
        d_esrc[d_ptr[d.y] + r.y] = s.y;
        d_esrc[d_ptr[d.z] + r.z] = s.z;
        d_esrc[d_ptr[d.w] + r.w] = s.w;
    }

    if (i < N_NODES * (HD / 4)) {
        int n = i >> 4;        // node
        int c = i & 15;        // float4 chunk
        float odeg = (float)d_deg_out[n]; if (odeg < 1.f) odeg = 1.f;
        float on = rsqrtf(odeg);
        if (c == 0) {
            d_onorm[n] = on;
            d_oinv[n]  = sqrtf(odeg);
            float ideg = (float)d_deg_in[n]; if (ideg < 1.f) ideg = 1.f;
            d_inorm[n] = rsqrtf(ideg);
        }
        const float* srcrow = (n < USER_NUM) ? (user + (size_t)n * HD)
                                             : (item + (size_t)(n - USER_NUM) * HD);
        float4 v = *(const float4*)(srcrow + c * 4);
        int gi = n * 32 + c * 2;
        d_gA[gi]     = __floats2half2_rn(v.x * on, v.y * on);
        d_gA[gi + 1] = __floats2half2_rn(v.z * on, v.w * on);
    }
}

// 4) aggregation layer. 4-lane groups: 8 edges in flight, 2 LDG.128 per edge row
//    (two 64B halves) -> 16 outstanding loads/warp. HADD2 accumulation.
//    LAYER 0: gA->gB; 1: gB->gC; 2: gC gather + final combine.
template <int LAYER>
__global__ void k_aggh(const float* __restrict__ user, const float* __restrict__ item,
                       float* __restrict__ out) {
    const int4* __restrict__ gin4  = (LAYER == 0) ? (const int4*)d_gA
                                   : (LAYER == 1) ? (const int4*)d_gB
                                                  : (const int4*)d_gC;
    int4* __restrict__ gout4 = (LAYER == 0) ? (int4*)d_gB : (int4*)d_gC;

    int warp = (blockIdx.x * blockDim.x + threadIdx.x) >> 5;
    int lane = threadIdx.x & 31;
    if (warp >= N_NODES) return;
    int n   = warp;
    int grp = lane >> 2;      // 0..7 : edge slot within batch of 8
    int sub = lane & 3;       // 0..3 : which int4 of the 64B half

    int p0 = d_ptr[n], p1 = d_ptr[n + 1];
    __half2 acc[8];
    #pragma unroll
    for (int k = 0; k < 8; k++) acc[k] = __float2half2_rn(0.f);

    for (int base = p0; base < p1; base += 32) {
        int navail = p1 - base; if (navail > 32) navail = 32;
        int e = (lane < navail) ? d_esrc[base + lane] : 0;
        #pragma unroll
        for (int j = 0; j < 4; j++) {
            int idx = j * 8 + grp;
            int s = __shfl_sync(0xffffffffu, e, idx);
            if (idx < navail) {
                const int4* rp = gin4 + (size_t)s * 8 + sub;
                int4 r0 = __ldg(rp);        // dims [sub*8,   sub*8+8)
                int4 r1 = __ldg(rp + 4);    // dims [32+sub*8, 32+sub*8+8)
                acc[0] = __hadd2(acc[0], *(__half2*)&r0.x);
                acc[1] = __hadd2(acc[1], *(__half2*)&r0.y);
                acc[2] = __hadd2(acc[2], *(__half2*)&r0.z);
                acc[3] = __hadd2(acc[3], *(__half2*)&r0.w);
                acc[4] = __hadd2(acc[4], *(__half2*)&r1.x);
                acc[5] = __hadd2(acc[5], *(__half2*)&r1.y);
                acc[6] = __hadd2(acc[6], *(__half2*)&r1.z);
                acc[7] = __hadd2(acc[7], *(__half2*)&r1.w);
            }
        }
    }

    // cross-group reduction (lane bits 2,3,4)
    #pragma unroll
    for (int m = 4; m <= 16; m <<= 1) {
        #pragma unroll
        for (int k = 0; k < 8; k++) {
            int t = __shfl_xor_sync(0xffffffffu, *(int*)&acc[k], m);
            acc[k] = __hadd2(acc[k], *(__half2*)&t);
        }
    }

    // lane now holds sums for dims [sub*8, sub*8+8) in acc[0..3]
    //                     and dims [32+sub*8, ...+8) in acc[4..7]
    float inn = d_inorm[n];
    float2 fx[8];
    #pragma unroll
    for (int k = 0; k < 8; k++) {
        fx[k] = __half22float2(acc[k]);
        fx[k].x *= inn; fx[k].y *= inn;
    }

    if (LAYER < 2) {
        // write next g = half(ex * onorm): grp 0 writes low half, grp 1 high half
        if (grp < 2) {
            float onn = d_onorm[n];
            int a = grp * 4;                         // acc base (0 or 4)
            __half2 h0 = __floats2half2_rn(fx[a+0].x * onn, fx[a+0].y * onn);
            __half2 h1 = __floats2half2_rn(fx[a+1].x * onn, fx[a+1].y * onn);
            __half2 h2 = __floats2half2_rn(fx[a+2].x * onn, fx[a+2].y * onn);
            __half2 h3 = __floats2half2_rn(fx[a+3].x * onn, fx[a+3].y * onn);
            int4 r;
            r.x = *(int*)&h0; r.y = *(int*)&h1; r.z = *(int*)&h2; r.w = *(int*)&h3;
            gout4[n * 8 + grp * 4 + sub] = r;
        }
    } else {
        // final combine: out = emb + oinv*(g1/2 + g2/3) + ex/4
        if (grp < 2) {
            const float4* erow = (n < USER_NUM)
                ? ((const float4*)user + (size_t)n * 16)
                : ((const float4*)item + (size_t)(n - USER_NUM) * 16);
            float oinv = d_oinv[n];
            float c1 = oinv * (1.0f / 2.0f);
            float c2 = oinv * (1.0f / 3.0f);
            int qbase = grp * 8 + sub * 2;   // float4 chunk (grp0: dims 0-31, grp1: 32-63)
            int abase = grp * 4;
            #pragma unroll
            for (int h = 0; h < 2; h++) {
                int q = qbase + h;
                float2 X = fx[abase + 2 * h];
                float2 Y = fx[abase + 2 * h + 1];
                const __half2* g1row = d_gB + n * 32 + q * 2;
                const __half2* g2row = d_gC + n * 32 + q * 2;
                float2 a1 = __half22float2(g1row[0]);
                float2 b1 = __half22float2(g1row[1]);
                float2 a2 = __half22float2(g2row[0]);
                float2 b2 = __half22float2(g2row[1]);
                float4 ev = __ldg(erow + q);
                float4 ov;
                ov.x = ev.x + a1.x * c1 + a2.x * c2 + X.x * 0.25f;
                ov.y = ev.y + a1.y * c1 + a2.y * c2 + X.y * 0.25f;
                ov.z = ev.z + b1.x * c1 + b2.x * c2 + Y.x * 0.25f;
                ov.w = ev.w + b1.y * c1 + b2.y * c2 + Y.y * 0.25f;
                ((float4*)(out + (size_t)n * HD))[q] = ov;
            }
        }
        if (lane == 0) {               // restore initial state for next replay
            d_deg_out[n] = 0;
            d_deg_in[n] = 0;
        }
    }
}

extern "C" void kernel_launch(void* const* d_in, const int* in_sizes, int n_in,
                              void* d_out, int out_size) {
    const float* user = (const float*)d_in[0];
    const float* item = (const float*)d_in[1];
    const int4*  src4 = (const int4*)d_in[2];
    const int4*  dst4 = (const int4*)d_in[3];
    float*       out  = (float*)d_out;

    const int EV_BLOCKS  = (N_EDGES / 4 + 255) / 256;          // 3907
    const int MRG_BLOCKS = (N_NODES * (HD / 4) + 255) / 256;   // 9375
    const int AGG_BLOCKS = (N_NODES * 32) / 256;               // 18750, exact

    k_hist<<<EV_BLOCKS, 256>>>(src4, dst4);                          // 1
    k_scanA<<<SCAN_NB, SCAN_BLK>>>();                                // 2
    k_scanC<<<SCAN_NB, SCAN_BLK>>>();                                // 3
    k_scatter_init<<<MRG_BLOCKS, 256>>>(src4, dst4, user, item);     // 4 <-- profiled
    k_aggh<0><<<AGG_BLOCKS, 256>>>(user, item, out);                 // 5: g0 -> g1
    k_aggh<1><<<AGG_BLOCKS, 256>>>(user, item, out);                 // 6: g1 -> g2
    k_aggh<2><<<AGG_BLOCKS, 256>>>(user, item, out);                 // 7: final combine
}

// round 14
// speedup vs baseline: 1.3374x; 1.3374x over previous
#include <cuda_runtime.h>
#include <cuda_fp16.h>

#define USER_NUM 100000
#define ITEM_NUM 50000
#define N_NODES  150000
#define HD       64
#define N_EDGES  4000000
#define SCAN_BLK 1024
#define SCAN_NB  ((N_NODES + SCAN_BLK - 1) / SCAN_BLK)   // 147

// ---- scratch (no allocation allowed -> __device__ globals) ----
// Globals start zeroed; the final layer's epilogue re-zeroes the degree
// counters so every (graph-replayed) call sees identical initial state.
__device__ int           d_deg_out[N_NODES];
__device__ int           d_deg_in[N_NODES];
__device__ int           d_blocksum[SCAN_NB];
__device__ int           d_ptr[N_NODES + 1];
__device__ unsigned char d_rank[N_EDGES];     // edge rank in dst bucket (max deg << 256)
__device__ int           d_esrc[N_EDGES];     // raw src index (CSR by dst)
__device__ float         d_onorm[N_NODES];    // odeg^-1/2
__device__ float         d_oinv[N_NODES];     // odeg^+1/2 (undo pre-scale)
__device__ float         d_inorm[N_NODES];    // ideg^-1/2
__device__ __half2       d_gA[N_NODES * 32];  // g0  (row = 64 half = 8 int4)
__device__ __half2       d_gB[N_NODES * 32];  // g1
__device__ __half2       d_gC[N_NODES * 32];  // g2

// 1) degree histograms; in-degree atomic's return = edge's bucket rank (u8-packed)
__global__ void k_hist(const int4* __restrict__ src4, const int4* __restrict__ dst4) {
    int i = blockIdx.x * blockDim.x + threadIdx.x;
    if (i >= N_EDGES / 4) return;
    int4 s = src4[i];
    int4 d = dst4[i];
    atomicAdd(&d_deg_out[s.x], 1); atomicAdd(&d_deg_out[s.y], 1);
    atomicAdd(&d_deg_out[s.z], 1); atomicAdd(&d_deg_out[s.w], 1);
    uchar4 r;
    r.x = (unsigned char)atomicAdd(&d_deg_in[d.x], 1);
    r.y = (unsigned char)atomicAdd(&d_deg_in[d.y], 1);
    r.z = (unsigned char)atomicAdd(&d_deg_in[d.z], 1);
    r.w = (unsigned char)atomicAdd(&d_deg_in[d.w], 1);
    ((uchar4*)d_rank)[i] = r;
}

// 2a) per-block sums of in-degree
__global__ void k_scanA() {
    __shared__ int sh[SCAN_BLK];
    int t = threadIdx.x;
    int i = blockIdx.x * SCAN_BLK + t;
    sh[t] = (i < N_NODES) ? d_deg_in[i] : 0;
    __syncthreads();
    for (int off = SCAN_BLK / 2; off > 0; off >>= 1) {
        if (t < off) sh[t] += sh[t + off];
        __syncthreads();
    }
    if (t == 0) d_blocksum[blockIdx.x] = sh[0];
}

// 2b+c) fused: per-block global offset from the 147 block sums, then
//        block-local exclusive scan -> ptr
__global__ void k_scanC() {
    __shared__ int sh[SCAN_BLK];
    __shared__ int bs[256];
    int t = threadIdx.x;
    bs[t & 255] = 0;
    __syncthreads();
    if (t < SCAN_NB) bs[t] = d_blocksum[t];
    __syncthreads();
    if (t == 0) {
        int run = 0;
        for (int b = 0; b < SCAN_NB; b++) { int v = bs[b]; bs[b] = run; run += v; }
    }
    __syncthreads();
    int blockoff = bs[blockIdx.x];

    int i = blockIdx.x * SCAN_BLK + t;
    int ideg = (i < N_NODES) ? d_deg_in[i] : 0;
    sh[t] = ideg;
    __syncthreads();
    for (int off = 1; off < SCAN_BLK; off <<= 1) {
        int v = sh[t];
        if (t >= off) v += sh[t - off];
        __syncthreads();
        sh[t] = v;
        __syncthreads();
    }
    if (i < N_NODES) {
        int excl = sh[t] - ideg + blockoff;
        d_ptr[i] = excl;
        if (i == N_NODES - 1) d_ptr[N_NODES] = excl + ideg;
    }
}

// 3) MERGED scatter + init (profiled 4th launch).
__global__ void k_scatter_init(const int4* __restrict__ src4,
                               const int4* __restrict__ dst4,
                               const float* __restrict__ user,
                               const float* __restrict__ item) {
    int i = blockIdx.x * blockDim.x + threadIdx.x;

    if (i < N_EDGES / 4) {
        int4 s = src4[i];
        int4 d = dst4[i];
        uchar4 r = ((const uchar4*)d_rank)[i];
        d_esrc[d_ptr[d.x] + r.x] = s.x;
        d_esrc[d_ptr[d.y] + r.y] = s.y;
        d_esrc[d_ptr[d.z] + r.z] = s.z;
        d_esrc[d_ptr[d.w] + r.w] = s.w;
    }

    if (i < N_NODES * (HD / 4)) {
        int n = i >> 4;        // node
        int c = i & 15;        // float4 chunk
        float odeg = (float)d_deg_out[n]; if (odeg < 1.f) odeg = 1.f;
        float on = rsqrtf(odeg);
        if (c == 0) {
            d_onorm[n] = on;
            d_oinv[n]  = sqrtf(odeg);
            float ideg = (float)d_deg_in[n]; if (ideg < 1.f) ideg = 1.f;
            d_inorm[n] = rsqrtf(ideg);
        }
        const float* srcrow = (n < USER_NUM) ? (user + (size_t)n * HD)
                                             : (item + (size_t)(n - USER_NUM) * HD);
        float4 v = *(const float4*)(srcrow + c * 4);
        int gi = n * 32 + c * 2;
        d_gA[gi]     = __floats2half2_rn(v.x * on, v.y * on);
        d_gA[gi + 1] = __floats2half2_rn(v.z * on, v.w * on);
    }
}

// 4) aggregation layer (R12 measured-best shape): 8-lane groups, one full-line
//    LDG.128 per edge (4 edges in flight), HADD2 accumulation.
//    LAYER 0: gA->gB; 1: gB->gC; 2: gC gather + final combine.
template <int LAYER>
__global__ void k_aggh(const float* __restrict__ user, const float* __restrict__ item,
                       float* __restrict__ out) {
    const int4* __restrict__ gin4  = (LAYER == 0) ? (const int4*)d_gA
                                   : (LAYER == 1) ? (const int4*)d_gB
                                                  : (const int4*)d_gC;
    int4* __restrict__ gout4 = (LAYER == 0) ? (int4*)d_gB : (int4*)d_gC;

    int warp = (blockIdx.x * blockDim.x + threadIdx.x) >> 5;
    int lane = threadIdx.x & 31;
    if (warp >= N_NODES) return;
    int n   = warp;
    int grp = lane >> 3;      // 0..3 : edge slot
    int sub = lane & 7;       // 0..7 : int4 within the 128B row

    int p0 = d_ptr[n], p1 = d_ptr[n + 1];
    __half2 acc0 = __float2half2_rn(0.f);
    __half2 acc1 = acc0, acc2 = acc0, acc3 = acc0;

    for (int base = p0; base < p1; base += 32) {
        int navail = p1 - base; if (navail > 32) navail = 32;
        int e = (lane < navail) ? d_esrc[base + lane] : 0;
        #pragma unroll
        for (int j = 0; j < 8; j++) {
            int idx = j * 4 + grp;
            int s = __shfl_sync(0xffffffffu, e, idx);
            if (idx < navail) {
                int4 r = __ldg(gin4 + (size_t)s * 8 + sub);
                acc0 = __hadd2(acc0, *(__half2*)&r.x);
                acc1 = __hadd2(acc1, *(__half2*)&r.y);
                acc2 = __hadd2(acc2, *(__half2*)&r.z);
                acc3 = __hadd2(acc3, *(__half2*)&r.w);
            }
        }
    }

    // cross-group reduction in half2 (lane bits 3,4)
    #pragma unroll
    for (int m = 8; m <= 16; m <<= 1) {
        int t0 = __shfl_xor_sync(0xffffffffu, *(int*)&acc0, m);
        int t1 = __shfl_xor_sync(0xffffffffu, *(int*)&acc1, m);
        int t2 = __shfl_xor_sync(0xffffffffu, *(int*)&acc2, m);
        int t3 = __shfl_xor_sync(0xffffffffu, *(int*)&acc3, m);
        acc0 = __hadd2(acc0, *(__half2*)&t0);
        acc1 = __hadd2(acc1, *(__half2*)&t1);
        acc2 = __hadd2(acc2, *(__half2*)&t2);
        acc3 = __hadd2(acc3, *(__half2*)&t3);
    }

    float2 f0 = __half22float2(acc0);
    float2 f1 = __half22float2(acc1);
    float2 f2 = __half22float2(acc2);
    float2 f3 = __half22float2(acc3);
    float inn = d_inorm[n];
    float ex[8] = { f0.x * inn, f0.y * inn, f1.x * inn, f1.y * inn,
                    f2.x * inn, f2.y * inn, f3.x * inn, f3.y * inn };

    if (LAYER < 2) {
        if (grp == 0) {
            float onn = d_onorm[n];
            __half2 h0 = __floats2half2_rn(ex[0] * onn, ex[1] * onn);
            __half2 h1 = __floats2half2_rn(ex[2] * onn, ex[3] * onn);
            __half2 h2 = __floats2half2_rn(ex[4] * onn, ex[5] * onn);
            __half2 h3 = __floats2half2_rn(ex[6] * onn, ex[7] * onn);
            int4 r;
            r.x = *(int*)&h0; r.y = *(int*)&h1; r.z = *(int*)&h2; r.w = *(int*)&h3;
            gout4[n * 8 + sub] = r;
        }
    } else {
        // final combine: out = emb + oinv*(g1/2 + g2/3) + ex/4
        if (grp < 2) {
            const float4* erow = (n < USER_NUM)
                ? ((const float4*)user + (size_t)n * 16)
                : ((const float4*)item + (size_t)(n - USER_NUM) * 16);
            int q = sub * 2 + grp;      // float4 index 0..15
            int o = grp * 4;
            float oinv = d_oinv[n];
            float c1 = oinv * (1.0f / 2.0f);
            float c2 = oinv * (1.0f / 3.0f);

            const __half2* g1row = d_gB + n * 32 + q * 2;
            const __half2* g2row = d_gC + n * 32 + q * 2;
            float2 a1 = __half22float2(g1row[0]);
            float2 b1 = __half22float2(g1row[1]);
            float2 a2 = __half22float2(g2row[0]);
            float2 b2 = __half22float2(g2row[1]);

            float4 ev = __ldg(erow + q);
            float4 ov;
            ov.x = ev.x + a1.x * c1 + a2.x * c2 + ex[o + 0] * 0.25f;
            ov.y = ev.y + a1.y * c1 + a2.y * c2 + ex[o + 1] * 0.25f;
            ov.z = ev.z + b1.x * c1 + b2.x * c2 + ex[o + 2] * 0.25f;
            ov.w = ev.w + b1.y * c1 + b2.y * c2 + ex[o + 3] * 0.25f;
            ((float4*)(out + (size_t)n * HD))[q] = ov;
        }
        if (lane == 0) {               // restore initial state for next replay
            d_deg_out[n] = 0;
            d_deg_in[n] = 0;
        }
    }
}

extern "C" void kernel_launch(void* const* d_in, const int* in_sizes, int n_in,
                              void* d_out, int out_size) {
    const float* user = (const float*)d_in[0];
    const float* item = (const float*)d_in[1];
    const int4*  src4 = (const int4*)d_in[2];
    const int4*  dst4 = (const int4*)d_in[3];
    float*       out  = (float*)d_out;

    const int EV_BLOCKS  = (N_EDGES / 4 + 255) / 256;          // 3907
    const int MRG_BLOCKS = (N_NODES * (HD / 4) + 255) / 256;   // 9375
    const int AGG_BLOCKS = (N_NODES * 32) / 256;               // 18750, exact

    k_hist<<<EV_BLOCKS, 256>>>(src4, dst4);                          // 1
    k_scanA<<<SCAN_NB, SCAN_BLK>>>();                                // 2
    k_scanC<<<SCAN_NB, SCAN_BLK>>>();                                // 3
    k_scatter_init<<<MRG_BLOCKS, 256>>>(src4, dst4, user, item);     // 4 <-- profiled
    k_aggh<0><<<AGG_BLOCKS, 256>>>(user, item, out);                 // 5: g0 -> g1
    k_aggh<1><<<AGG_BLOCKS, 256>>>(user, item, out);                 // 6: g1 -> g2
    k_aggh<2><<<AGG_BLOCKS, 256>>>(user, item, out);                 // 7: final combine
}

// round 15
// speedup vs baseline: 1.4599x; 1.0916x over previous
#include <cuda_runtime.h>
#include <cuda_fp16.h>

#define USER_NUM 100000
#define ITEM_NUM 50000
#define N_NODES  150000
#define HD       64
#define N_EDGES  4000000
#define SCAN_BLK 1024
#define SCAN_NB  ((N_NODES + SCAN_BLK - 1) / SCAN_BLK)   // 147

// ---- scratch (no allocation allowed -> __device__ globals) ----
// Globals start zeroed; the final layer's epilogue re-zeroes the degree
// counters so every (graph-replayed) call sees identical initial state.
__device__ int           d_deg_out[N_NODES];
__device__ int           d_deg_in[N_NODES];
__device__ int           d_blocksum[SCAN_NB];
__device__ int           d_ptr[N_NODES + 1];
__device__ unsigned char d_rank[N_EDGES];     // edge rank in dst bucket (max deg << 256)
__device__ int           d_esrc[N_EDGES];     // raw src index (CSR by dst)
__device__ float         d_onorm[N_NODES];    // odeg^-1/2
__device__ float         d_oinv[N_NODES];     // odeg^+1/2 (undo pre-scale)
__device__ float         d_inorm[N_NODES];    // ideg^-1/2
__device__ __half2       d_gA[N_NODES * 32];  // g0  (row = 64 half = 8 int4)
__device__ __half2       d_gB[N_NODES * 32];  // g1
__device__ __half2       d_gC[N_NODES * 32];  // g2

// 1) degree histograms; in-degree atomic's return = edge's bucket rank (u8-packed)
__global__ void k_hist(const int4* __restrict__ src4, const int4* __restrict__ dst4) {
    int i = blockIdx.x * blockDim.x + threadIdx.x;
    if (i >= N_EDGES / 4) return;
    int4 s = src4[i];
    int4 d = dst4[i];
    atomicAdd(&d_deg_out[s.x], 1); atomicAdd(&d_deg_out[s.y], 1);
    atomicAdd(&d_deg_out[s.z], 1); atomicAdd(&d_deg_out[s.w], 1);
    uchar4 r;
    r.x = (unsigned char)atomicAdd(&d_deg_in[d.x], 1);
    r.y = (unsigned char)atomicAdd(&d_deg_in[d.y], 1);
    r.z = (unsigned char)atomicAdd(&d_deg_in[d.z], 1);
    r.w = (unsigned char)atomicAdd(&d_deg_in[d.w], 1);
    ((uchar4*)d_rank)[i] = r;
}

// 2a) per-block sums of in-degree
__global__ void k_scanA() {
    __shared__ int sh[SCAN_BLK];
    int t = threadIdx.x;
    int i = blockIdx.x * SCAN_BLK + t;
    sh[t] = (i < N_NODES) ? d_deg_in[i] : 0;
    __syncthreads();
    for (int off = SCAN_BLK / 2; off > 0; off >>= 1) {
        if (t < off) sh[t] += sh[t + off];
        __syncthreads();
    }
    if (t == 0) d_blocksum[blockIdx.x] = sh[0];
}

// 2b+c) fused: per-block global offset from the 147 block sums, then
//        block-local exclusive scan -> ptr
__global__ void k_scanC() {
    __shared__ int sh[SCAN_BLK];
    __shared__ int bs[256];
    int t = threadIdx.x;
    bs[t & 255] = 0;
    __syncthreads();
    if (t < SCAN_NB) bs[t] = d_blocksum[t];
    __syncthreads();
    if (t == 0) {
        int run = 0;
        for (int b = 0; b < SCAN_NB; b++) { int v = bs[b]; bs[b] = run; run += v; }
    }
    __syncthreads();
    int blockoff = bs[blockIdx.x];

    int i = blockIdx.x * SCAN_BLK + t;
    int ideg = (i < N_NODES) ? d_deg_in[i] : 0;
    sh[t] = ideg;
    __syncthreads();
    for (int off = 1; off < SCAN_BLK; off <<= 1) {
        int v = sh[t];
        if (t >= off) v += sh[t - off];
        __syncthreads();
        sh[t] = v;
        __syncthreads();
    }
    if (i < N_NODES) {
        int excl = sh[t] - ideg + blockoff;
        d_ptr[i] = excl;
        if (i == N_NODES - 1) d_ptr[N_NODES] = excl + ideg;
    }
}

// 3) MERGED scatter + init (profiled 4th launch).
__global__ void k_scatter_init(const int4* __restrict__ src4,
                               const int4* __restrict__ dst4,
                               const float* __restrict__ user,
                               const float* __restrict__ item) {
    int i = blockIdx.x * blockDim.x + threadIdx.x;

    if (i < N_EDGES / 4) {
        int4 s = src4[i];
        int4 d = dst4[i];
        uchar4 r = ((const uchar4*)d_rank)[i];
        d_esrc[d_ptr[d.x] + r.x] = s.x;
        d_esrc[d_ptr[d.y] + r.y] = s.y;
        d_esrc[d_ptr[d.z] + r.z] = s.z;
        d_esrc[d_ptr[d.w] + r.w] = s.w;
    }

    if (i < N_NODES * (HD / 4)) {
        int n = i >> 4;        // node
        int c = i & 15;        // float4 chunk
        float odeg = (float)d_deg_out[n]; if (odeg < 1.f) odeg = 1.f;
        float on = rsqrtf(odeg);
        if (c == 0) {
            d_onorm[n] = on;
            d_oinv[n]  = sqrtf(odeg);
            float ideg = (float)d_deg_in[n]; if (ideg < 1.f) ideg = 1.f;
            d_inorm[n] = rsqrtf(ideg);
        }
        const float* srcrow = (n < USER_NUM) ? (user + (size_t)n * HD)
                                             : (item + (size_t)(n - USER_NUM) * HD);
        float4 v = *(const float4*)(srcrow + c * 4);
        int gi = n * 32 + c * 2;
        d_gA[gi]     = __floats2half2_rn(v.x * on, v.y * on);
        d_gA[gi + 1] = __floats2half2_rn(v.z * on, v.w * on);
    }
}

// 4) aggregation layer: 8-lane groups, one full-line LDG.128 per edge,
//    DIRECT per-group index loads (no shfl — group lanes broadcast-load the
//    same esrc word; the 8 j-iterations hit one 128B esrc line).
//    LAYER 0: gA->gB; 1: gB->gC; 2: gC gather + final combine.
template <int LAYER>
__global__ void k_aggh(const float* __restrict__ user, const float* __restrict__ item,
                       float* __restrict__ out) {
    const int4* __restrict__ gin4  = (LAYER == 0) ? (const int4*)d_gA
                                   : (LAYER == 1) ? (const int4*)d_gB
                                                  : (const int4*)d_gC;
    int4* __restrict__ gout4 = (LAYER == 0) ? (int4*)d_gB : (int4*)d_gC;

    int warp = (blockIdx.x * blockDim.x + threadIdx.x) >> 5;
    int lane = threadIdx.x & 31;
    if (warp >= N_NODES) return;
    int n   = warp;
    int grp = lane >> 3;      // 0..3 : edge slot
    int sub = lane & 7;       // 0..7 : int4 within the 128B row

    int p0 = d_ptr[n], p1 = d_ptr[n + 1];
    __half2 acc0 = __float2half2_rn(0.f);
    __half2 acc1 = acc0, acc2 = acc0, acc3 = acc0;

    for (int base = p0; base < p1; base += 32) {
        int navail = p1 - base; if (navail > 32) navail = 32;
        #pragma unroll
        for (int j = 0; j < 8; j++) {
            int idx = j * 4 + grp;
            if (idx < navail) {
                int s = __ldg(d_esrc + base + idx);      // group-broadcast load
                int4 r = __ldg(gin4 + (size_t)s * 8 + sub);
                acc0 = __hadd2(acc0, *(__half2*)&r.x);
                acc1 = __hadd2(acc1, *(__half2*)&r.y);
                acc2 = __hadd2(acc2, *(__half2*)&r.z);
                acc3 = __hadd2(acc3, *(__half2*)&r.w);
            }
        }
    }

    // cross-group reduction in half2 (lane bits 3,4)
    #pragma unroll
    for (int m = 8; m <= 16; m <<= 1) {
        int t0 = __shfl_xor_sync(0xffffffffu, *(int*)&acc0, m);
        int t1 = __shfl_xor_sync(0xffffffffu, *(int*)&acc1, m);
        int t2 = __shfl_xor_sync(0xffffffffu, *(int*)&acc2, m);
        int t3 = __shfl_xor_sync(0xffffffffu, *(int*)&acc3, m);
        acc0 = __hadd2(acc0, *(__half2*)&t0);
        acc1 = __hadd2(acc1, *(__half2*)&t1);
        acc2 = __hadd2(acc2, *(__half2*)&t2);
        acc3 = __hadd2(acc3, *(__half2*)&t3);
    }

    float2 f0 = __half22float2(acc0);
    float2 f1 = __half22float2(acc1);
    float2 f2 = __half22float2(acc2);
    float2 f3 = __half22float2(acc3);
    float inn = d_inorm[n];
    float ex[8] = { f0.x * inn, f0.y * inn, f1.x * inn, f1.y * inn,
                    f2.x * inn, f2.y * inn, f3.x * inn, f3.y * inn };

    if (LAYER < 2) {
        if (grp == 0) {
            float onn = d_onorm[n];
            __half2 h0 = __floats2half2_rn(ex[0] * onn, ex[1] * onn);
            __half2 h1 = __floats2half2_rn(ex[2] * onn, ex[3] * onn);
            __half2 h2 = __floats2half2_rn(ex[4] * onn, ex[5] * onn);
            __half2 h3 = __floats2half2_rn(ex[6] * onn, ex[7] * onn);
            int4 r;
            r.x = *(int*)&h0; r.y = *(int*)&h1; r.z = *(int*)&h2; r.w = *(int*)&h3;
            gout4[n * 8 + sub] = r;
        }
    } else {
        // final combine: out = emb + oinv*(g1/2 + g2/3) + ex/4
        if (grp < 2) {
            const float4* erow = (n < USER_NUM)
                ? ((const float4*)user + (size_t)n * 16)
                : ((const float4*)item + (size_t)(n - USER_NUM) * 16);
            int q = sub * 2 + grp;      // float4 index 0..15
            int o = grp * 4;
            float oinv = d_oinv[n];
            float c1 = oinv * (1.0f / 2.0f);
            float c2 = oinv * (1.0f / 3.0f);

            const __half2* g1row = d_gB + n * 32 + q * 2;
            const __half2* g2row = d_gC + n * 32 + q * 2;
            float2 a1 = __half22float2(g1row[0]);
            float2 b1 = __half22float2(g1row[1]);
            float2 a2 = __half22float2(g2row[0]);
            float2 b2 = __half22float2(g2row[1]);

            float4 ev = __ldg(erow + q);
            float4 ov;
            ov.x = ev.x + a1.x * c1 + a2.x * c2 + ex[o + 0] * 0.25f;
            ov.y = ev.y + a1.y * c1 + a2.y * c2 + ex[o + 1] * 0.25f;
            ov.z = ev.z + b1.x * c1 + b2.x * c2 + ex[o + 2] * 0.25f;
            ov.w = ev.w + b1.y * c1 + b2.y * c2 + ex[o + 3] * 0.25f;
            ((float4*)(out + (size_t)n * HD))[q] = ov;
        }
        if (lane == 0) {               // restore initial state for next replay
            d_deg_out[n] = 0;
            d_deg_in[n] = 0;
        }
    }
}

extern "C" void kernel_launch(void* const* d_in, const int* in_sizes, int n_in,
                              void* d_out, int out_size) {
    const float* user = (const float*)d_in[0];
    const float* item = (const float*)d_in[1];
    const int4*  src4 = (const int4*)d_in[2];
    const int4*  dst4 = (const int4*)d_in[3];
    float*       out  = (float*)d_out;

    const int EV_BLOCKS  = (N_EDGES / 4 + 255) / 256;          // 3907
    const int MRG_BLOCKS = (N_NODES * (HD / 4) + 255) / 256;   // 9375
    const int AGG_BLOCKS = (N_NODES * 32) / 256;               // 18750, exact

    k_hist<<<EV_BLOCKS, 256>>>(src4, dst4);                          // 1
    k_scanA<<<SCAN_NB, SCAN_BLK>>>();                                // 2
    k_scanC<<<SCAN_NB, SCAN_BLK>>>();                                // 3
    k_scatter_init<<<MRG_BLOCKS, 256>>>(src4, dst4, user, item);     // 4 <-- profiled
    k_aggh<0><<<AGG_BLOCKS, 256>>>(user, item, out);                 // 5: g0 -> g1
    k_aggh<1><<<AGG_BLOCKS, 256>>>(user, item, out);                 // 6: g1 -> g2
    k_aggh<2><<<AGG_BLOCKS, 256>>>(user, item, out);                 // 7: final combine
}

// round 16
// speedup vs baseline: 1.4749x; 1.0103x over previous
#include <cuda_runtime.h>
#include <cuda_fp16.h>

#define USER_NUM 100000
#define ITEM_NUM 50000
#define N_NODES  150000
#define HD       64
#define N_EDGES  4000000
#define SCAN_BLK 1024
#define SCAN_NB  ((N_NODES + SCAN_BLK - 1) / SCAN_BLK)   // 147

// ---- scratch (no allocation allowed -> __device__ globals) ----
// Globals start zeroed; the final layer's epilogue re-zeroes the degree
// counters so every (graph-replayed) call sees identical initial state.
__device__ int           d_deg_out[N_NODES];
__device__ int           d_deg_in[N_NODES];
__device__ int           d_blocksum[SCAN_NB];
__device__ int           d_ptr[N_NODES + 1];
__device__ unsigned char d_rank[N_EDGES];     // edge rank in dst bucket (max deg << 256)
__device__ int           d_esrc[N_EDGES];     // raw src index (CSR by dst)
__device__ float         d_onorm[N_NODES];    // odeg^-1/2
__device__ float         d_oinv[N_NODES];     // odeg^+1/2 (undo pre-scale)
__device__ float         d_inorm[N_NODES];    // ideg^-1/2
__device__ __half2       d_gA[N_NODES * 32];  // g0  (row = 64 half = 8 int4)
__device__ __half2       d_gB[N_NODES * 32];  // g1
__device__ __half2       d_gC[N_NODES * 32];  // g2

// 1) degree histograms; in-degree atomic's return = edge's bucket rank (u8-packed)
__global__ void k_hist(const int4* __restrict__ src4, const int4* __restrict__ dst4) {
    int i = blockIdx.x * blockDim.x + threadIdx.x;
    if (i >= N_EDGES / 4) return;
    int4 s = src4[i];
    int4 d = dst4[i];
    atomicAdd(&d_deg_out[s.x], 1); atomicAdd(&d_deg_out[s.y], 1);
    atomicAdd(&d_deg_out[s.z], 1); atomicAdd(&d_deg_out[s.w], 1);
    uchar4 r;
    r.x = (unsigned char)atomicAdd(&d_deg_in[d.x], 1);
    r.y = (unsigned char)atomicAdd(&d_deg_in[d.y], 1);
    r.z = (unsigned char)atomicAdd(&d_deg_in[d.z], 1);
    r.w = (unsigned char)atomicAdd(&d_deg_in[d.w], 1);
    ((uchar4*)d_rank)[i] = r;
}

// 2a) per-block sums of in-degree
__global__ void k_scanA() {
    __shared__ int sh[SCAN_BLK];
    int t = threadIdx.x;
    int i = blockIdx.x * SCAN_BLK + t;
    sh[t] = (i < N_NODES) ? d_deg_in[i] : 0;
    __syncthreads();
    for (int off = SCAN_BLK / 2; off > 0; off >>= 1) {
        if (t < off) sh[t] += sh[t + off];
        __syncthreads();
    }
    if (t == 0) d_blocksum[blockIdx.x] = sh[0];
}

// 2b+c) fused: per-block global offset from the 147 block sums, then
//        block-local exclusive scan -> ptr
__global__ void k_scanC() {
    __shared__ int sh[SCAN_BLK];
    __shared__ int bs[256];
    int t = threadIdx.x;
    bs[t & 255] = 0;
    __syncthreads();
    if (t < SCAN_NB) bs[t] = d_blocksum[t];
    __syncthreads();
    if (t == 0) {
        int run = 0;
        for (int b = 0; b < SCAN_NB; b++) { int v = bs[b]; bs[b] = run; run += v; }
    }
    __syncthreads();
    int blockoff = bs[blockIdx.x];

    int i = blockIdx.x * SCAN_BLK + t;
    int ideg = (i < N_NODES) ? d_deg_in[i] : 0;
    sh[t] = ideg;
    __syncthreads();
    for (int off = 1; off < SCAN_BLK; off <<= 1) {
        int v = sh[t];
        if (t >= off) v += sh[t - off];
        __syncthreads();
        sh[t] = v;
        __syncthreads();
    }
    if (i < N_NODES) {
        int excl = sh[t] - ideg + blockoff;
        d_ptr[i] = excl;
        if (i == N_NODES - 1) d_ptr[N_NODES] = excl + ideg;
    }
}

// 3) MERGED scatter + init (profiled 4th launch).
__global__ void k_scatter_init(const int4* __restrict__ src4,
                               const int4* __restrict__ dst4,
                               const float* __restrict__ user,
                               const float* __restrict__ item) {
    int i = blockIdx.x * blockDim.x + threadIdx.x;

    if (i < N_EDGES / 4) {
        int4 s = src4[i];
        int4 d = dst4[i];
        uchar4 r = ((const uchar4*)d_rank)[i];
        d_esrc[d_ptr[d.x] + r.x] = s.x;
        d_esrc[d_ptr[d.y] + r.y] = s.y;
        d_esrc[d_ptr[d.z] + r.z] = s.z;
        d_esrc[d_ptr[d.w] + r.w] = s.w;
    }

    if (i < N_NODES * (HD / 4)) {
        int n = i >> 4;        // node
        int c = i & 15;        // float4 chunk
        float odeg = (float)d_deg_out[n]; if (odeg < 1.f) odeg = 1.f;
        float on = rsqrtf(odeg);
        if (c == 0) {
            d_onorm[n] = on;
            d_oinv[n]  = sqrtf(odeg);
            float ideg = (float)d_deg_in[n]; if (ideg < 1.f) ideg = 1.f;
            d_inorm[n] = rsqrtf(ideg);
        }
        const float* srcrow = (n < USER_NUM) ? (user + (size_t)n * HD)
                                             : (item + (size_t)(n - USER_NUM) * HD);
        float4 v = *(const float4*)(srcrow + c * 4);
        int gi = n * 32 + c * 2;
        d_gA[gi]     = __floats2half2_rn(v.x * on, v.y * on);
        d_gA[gi + 1] = __floats2half2_rn(v.z * on, v.w * on);
    }
}

// 4) aggregation layer: 8-lane groups, one full-line LDG.128 per edge, direct
//    group-broadcast index loads, DUAL accumulator banks (even/odd j) to halve
//    the HADD2 RAW chains, counted per-group inner loop.
//    LAYER 0: gA->gB; 1: gB->gC; 2: gC gather + final combine.
template <int LAYER>
__global__ void k_aggh(const float* __restrict__ user, const float* __restrict__ item,
                       float* __restrict__ out) {
    const int4* __restrict__ gin4  = (LAYER == 0) ? (const int4*)d_gA
                                   : (LAYER == 1) ? (const int4*)d_gB
                                                  : (const int4*)d_gC;
    int4* __restrict__ gout4 = (LAYER == 0) ? (int4*)d_gB : (int4*)d_gC;

    int warp = (blockIdx.x * blockDim.x + threadIdx.x) >> 5;
    int lane = threadIdx.x & 31;
    if (warp >= N_NODES) return;
    int n   = warp;
    int grp = lane >> 3;      // 0..3 : edge slot
    int sub = lane & 7;       // 0..7 : int4 within the 128B row

    int p0 = d_ptr[n], p1 = d_ptr[n + 1];
    __half2 z = __float2half2_rn(0.f);
    __half2 e0 = z, e1 = z, e2 = z, e3 = z;   // even-j bank
    __half2 o0 = z, o1 = z, o2 = z, o3 = z;   // odd-j bank

    for (int base = p0; base < p1; base += 32) {
        int navail = p1 - base; if (navail > 32) navail = 32;
        // group g handles idx = j*4 + grp for j in [0, nj)
        int nj = (navail - grp + 3) >> 2;     // grp < navail guaranteed when nj > 0
        const int* ep = d_esrc + base + grp;
        #pragma unroll
        for (int j = 0; j < 8; j++) {
            if (j < nj) {
                int s = __ldg(ep + j * 4);                 // group-broadcast load
                int4 r = __ldg(gin4 + (size_t)s * 8 + sub);
                if (j & 1) {
                    o0 = __hadd2(o0, *(__half2*)&r.x);
                    o1 = __hadd2(o1, *(__half2*)&r.y);
                    o2 = __hadd2(o2, *(__half2*)&r.z);
                    o3 = __hadd2(o3, *(__half2*)&r.w);
                } else {
                    e0 = __hadd2(e0, *(__half2*)&r.x);
                    e1 = __hadd2(e1, *(__half2*)&r.y);
                    e2 = __hadd2(e2, *(__half2*)&r.z);
                    e3 = __hadd2(e3, *(__half2*)&r.w);
                }
            }
        }
    }

    __half2 acc0 = __hadd2(e0, o0);
    __half2 acc1 = __hadd2(e1, o1);
    __half2 acc2 = __hadd2(e2, o2);
    __half2 acc3 = __hadd2(e3, o3);

    // cross-group reduction in half2 (lane bits 3,4)
    #pragma unroll
    for (int m = 8; m <= 16; m <<= 1) {
        int t0 = __shfl_xor_sync(0xffffffffu, *(int*)&acc0, m);
        int t1 = __shfl_xor_sync(0xffffffffu, *(int*)&acc1, m);
        int t2 = __shfl_xor_sync(0xffffffffu, *(int*)&acc2, m);
        int t3 = __shfl_xor_sync(0xffffffffu, *(int*)&acc3, m);
        acc0 = __hadd2(acc0, *(__half2*)&t0);
        acc1 = __hadd2(acc1, *(__half2*)&t1);
        acc2 = __hadd2(acc2, *(__half2*)&t2);
        acc3 = __hadd2(acc3, *(__half2*)&t3);
    }

    float2 f0 = __half22float2(acc0);
    float2 f1 = __half22float2(acc1);
    float2 f2 = __half22float2(acc2);
    float2 f3 = __half22float2(acc3);
    float inn = d_inorm[n];
    float ex[8] = { f0.x * inn, f0.y * inn, f1.x * inn, f1.y * inn,
                    f2.x * inn, f2.y * inn, f3.x * inn, f3.y * inn };

    if (LAYER < 2) {
        if (grp == 0) {
            float onn = d_onorm[n];
            __half2 h0 = __floats2half2_rn(ex[0] * onn, ex[1] * onn);
            __half2 h1 = __floats2half2_rn(ex[2] * onn, ex[3] * onn);
            __half2 h2 = __floats2half2_rn(ex[4] * onn, ex[5] * onn);
            __half2 h3 = __floats2half2_rn(ex[6] * onn, ex[7] * onn);
            int4 r;
            r.x = *(int*)&h0; r.y = *(int*)&h1; r.z = *(int*)&h2; r.w = *(int*)&h3;
            gout4[n * 8 + sub] = r;
        }
    } else {
        // final combine: out = emb + oinv*(g1/2 + g2/3) + ex/4
        if (grp < 2) {
            const float4* erow = (n < USER_NUM)
                ? ((const float4*)user + (size_t)n * 16)
                : ((const float4*)item + (size_t)(n - USER_NUM) * 16);
            int q = sub * 2 + grp;      // float4 index 0..15
            int o = grp * 4;
            float oinv = d_oinv[n];
            float c1 = oinv * (1.0f / 2.0f);
            float c2 = oinv * (1.0f / 3.0f);

            const __half2* g1row = d_gB + n * 32 + q * 2;
            const __half2* g2row = d_gC + n * 32 + q * 2;
            float2 a1 = __half22float2(g1row[0]);
            float2 b1 = __half22float2(g1row[1]);
            float2 a2 = __half22float2(g2row[0]);
            float2 b2 = __half22float2(g2row[1]);

            float4 ev = __ldg(erow + q);
            float4 ov;
            ov.x = ev.x + a1.x * c1 + a2.x * c2 + ex[o + 0] * 0.25f;
            ov.y = ev.y + a1.y * c1 + a2.y * c2 + ex[o + 1] * 0.25f;
            ov.z = ev.z + b1.x * c1 + b2.x * c2 + ex[o + 2] * 0.25f;
            ov.w = ev.w + b1.y * c1 + b2.y * c2 + ex[o + 3] * 0.25f;
            ((float4*)(out + (size_t)n * HD))[q] = ov;
        }
        if (lane == 0) {               // restore initial state for next replay
            d_deg_out[n] = 0;
            d_deg_in[n] = 0;
        }
    }
}

extern "C" void kernel_launch(void* const* d_in, const int* in_sizes, int n_in,
                              void* d_out, int out_size) {
    const float* user = (const float*)d_in[0];
    const float* item = (const float*)d_in[1];
    const int4*  src4 = (const int4*)d_in[2];
    const int4*  dst4 = (const int4*)d_in[3];
    float*       out  = (float*)d_out;

    const int EV_BLOCKS  = (N_EDGES / 4 + 255) / 256;          // 3907
    const int MRG_BLOCKS = (N_NODES * (HD / 4) + 255) / 256;   // 9375
    const int AGG_BLOCKS = (N_NODES * 32) / 256;               // 18750, exact

    k_hist<<<EV_BLOCKS, 256>>>(src4, dst4);                          // 1
    k_scanA<<<SCAN_NB, SCAN_BLK>>>();                                // 2
    k_scanC<<<SCAN_NB, SCAN_BLK>>>();                                // 3
    k_scatter_init<<<MRG_BLOCKS, 256>>>(src4, dst4, user, item);     // 4 <-- profiled
    k_aggh<0><<<AGG_BLOCKS, 256>>>(user, item, out);                 // 5: g0 -> g1
    k_aggh<1><<<AGG_BLOCKS, 256>>>(user, item, out);                 // 6: g1 -> g2
    k_aggh<2><<<AGG_BLOCKS, 256>>>(user, item, out);                 // 7: final combine
}

// round 17
// speedup vs baseline: 1.5194x; 1.0302x over previous
#include <cuda_runtime.h>
#include <cuda_fp16.h>

#define USER_NUM 100000
#define ITEM_NUM 50000
#define N_NODES  150000
#define HD       64
#define N_EDGES  4000000
#define SCAN_BLK 1024
#define SCAN_NB  ((N_NODES + SCAN_BLK - 1) / SCAN_BLK)   // 147

// ---- scratch (no allocation allowed -> __device__ globals) ----
// Globals start zeroed; the final layer's epilogue re-zeroes the degree
// counters so every (graph-replayed) call sees identical initial state.
__device__ int           d_deg_out[N_NODES];
__device__ int           d_deg_in[N_NODES];
__device__ int           d_blocksum[SCAN_NB];
__device__ int           d_ptr[N_NODES + 1];
__device__ unsigned char d_rank[N_EDGES];     // edge rank in dst bucket (max deg << 256)
__device__ int           d_esrc[N_EDGES];     // src * 8 (int4 row base, CSR by dst)
__device__ float         d_onorm[N_NODES];    // odeg^-1/2
__device__ float         d_oinv[N_NODES];     // odeg^+1/2 (undo pre-scale)
__device__ float         d_inorm[N_NODES];    // ideg^-1/2
__device__ __half2       d_gA[N_NODES * 32];  // g0  (row = 64 half = 8 int4)
__device__ __half2       d_gB[N_NODES * 32];  // g1
__device__ __half2       d_gC[N_NODES * 32];  // g2

// 1) degree histograms; in-degree atomic's return = edge's bucket rank (u8-packed)
__global__ void k_hist(const int4* __restrict__ src4, const int4* __restrict__ dst4) {
    int i = blockIdx.x * blockDim.x + threadIdx.x;
    if (i >= N_EDGES / 4) return;
    int4 s = src4[i];
    int4 d = dst4[i];
    atomicAdd(&d_deg_out[s.x], 1); atomicAdd(&d_deg_out[s.y], 1);
    atomicAdd(&d_deg_out[s.z], 1); atomicAdd(&d_deg_out[s.w], 1);
    uchar4 r;
    r.x = (unsigned char)atomicAdd(&d_deg_in[d.x], 1);
    r.y = (unsigned char)atomicAdd(&d_deg_in[d.y], 1);
    r.z = (unsigned char)atomicAdd(&d_deg_in[d.z], 1);
    r.w = (unsigned char)atomicAdd(&d_deg_in[d.w], 1);
    ((uchar4*)d_rank)[i] = r;
}

// 2a) per-block sums of in-degree
__global__ void k_scanA() {
    __shared__ int sh[SCAN_BLK];
    int t = threadIdx.x;
    int i = blockIdx.x * SCAN_BLK + t;
    sh[t] = (i < N_NODES) ? d_deg_in[i] : 0;
    __syncthreads();
    for (int off = SCAN_BLK / 2; off > 0; off >>= 1) {
        if (t < off) sh[t] += sh[t + off];
        __syncthreads();
    }
    if (t == 0) d_blocksum[blockIdx.x] = sh[0];
}

// 2b+c) fused: per-block global offset from the 147 block sums, then
//        block-local exclusive scan -> ptr
__global__ void k_scanC() {
    __shared__ int sh[SCAN_BLK];
    __shared__ int bs[256];
    int t = threadIdx.x;
    bs[t & 255] = 0;
    __syncthreads();
    if (t < SCAN_NB) bs[t] = d_blocksum[t];
    __syncthreads();
    if (t == 0) {
        int run = 0;
        for (int b = 0; b < SCAN_NB; b++) { int v = bs[b]; bs[b] = run; run += v; }
    }
    __syncthreads();
    int blockoff = bs[blockIdx.x];

    int i = blockIdx.x * SCAN_BLK + t;
    int ideg = (i < N_NODES) ? d_deg_in[i] : 0;
    sh[t] = ideg;
    __syncthreads();
    for (int off = 1; off < SCAN_BLK; off <<= 1) {
        int v = sh[t];
        if (t >= off) v += sh[t - off];
        __syncthreads();
        sh[t] = v;
        __syncthreads();
    }
    if (i < N_NODES) {
        int excl = sh[t] - ideg + blockoff;
        d_ptr[i] = excl;
        if (i == N_NODES - 1) d_ptr[N_NODES] = excl + ideg;
    }
}

// 3) MERGED scatter + init (profiled 4th launch).
//    Scatter stores src*8 so the agg gather needs no index scaling.
__global__ void k_scatter_init(const int4* __restrict__ src4,
                               const int4* __restrict__ dst4,
                               const float* __restrict__ user,
                               const float* __restrict__ item) {
    int i = blockIdx.x * blockDim.x + threadIdx.x;

    if (i < N_EDGES / 4) {
        int4 s = src4[i];
        int4 d = dst4[i];
        uchar4 r = ((const uchar4*)d_rank)[i];
        d_esrc[__ldg(d_ptr + d.x) + r.x] = s.x << 3;
        d_esrc[__ldg(d_ptr + d.y) + r.y] = s.y << 3;
        d_esrc[__ldg(d_ptr + d.z) + r.z] = s.z << 3;
        d_esrc[__ldg(d_ptr + d.w) + r.w] = s.w << 3;
    }

    if (i < N_NODES * (HD / 4)) {
        int n = i >> 4;        // node
        int c = i & 15;        // float4 chunk
        float odeg = (float)d_deg_out[n]; if (odeg < 1.f) odeg = 1.f;
        float on = rsqrtf(odeg);
        if (c == 0) {
            d_onorm[n] = on;
            d_oinv[n]  = sqrtf(odeg);
            float ideg = (float)d_deg_in[n]; if (ideg < 1.f) ideg = 1.f;
            d_inorm[n] = rsqrtf(ideg);
        }
        const float* srcrow = (n < USER_NUM) ? (user + (size_t)n * HD)
                                             : (item + (size_t)(n - USER_NUM) * HD);
        float4 v = *(const float4*)(srcrow + c * 4);
        int gi = n * 32 + c * 2;
        d_gA[gi]     = __floats2half2_rn(v.x * on, v.y * on);
        d_gA[gi + 1] = __floats2half2_rn(v.z * on, v.w * on);
    }
}

// 4) aggregation layer: 8-lane groups, one full-line LDG.128 per edge, direct
//    group-broadcast index loads (pre-shifted indices: no address IMAD), dual
//    accumulator banks (even/odd j), counted per-group inner loop.
//    LAYER 0: gA->gB; 1: gB->gC; 2: gC gather + final combine.
template <int LAYER>
__global__ void k_aggh(const float* __restrict__ user, const float* __restrict__ item,
                       float* __restrict__ out) {
    const int4* __restrict__ gin4  = (LAYER == 0) ? (const int4*)d_gA
                                   : (LAYER == 1) ? (const int4*)d_gB
                                                  : (const int4*)d_gC;
    int4* __restrict__ gout4 = (LAYER == 0) ? (int4*)d_gB : (int4*)d_gC;

    int warp = (blockIdx.x * blockDim.x + threadIdx.x) >> 5;
    int lane = threadIdx.x & 31;
    if (warp >= N_NODES) return;
    int n   = warp;
    int grp = lane >> 3;      // 0..3 : edge slot
    int sub = lane & 7;       // 0..7 : int4 within the 128B row

    int p0 = d_ptr[n], p1 = d_ptr[n + 1];
    __half2 z = __float2half2_rn(0.f);
    __half2 e0 = z, e1 = z, e2 = z, e3 = z;   // even-j bank
    __half2 o0 = z, o1 = z, o2 = z, o3 = z;   // odd-j bank

    const int4* __restrict__ gsub = gin4 + sub;

    for (int base = p0; base < p1; base += 32) {
        int navail = p1 - base; if (navail > 32) navail = 32;
        int nj = (navail - grp + 3) >> 2;     // iterations for this group
        const int* ep = d_esrc + base + grp;
        #pragma unroll
        for (int j = 0; j < 8; j++) {
            if (j < nj) {
                int s = __ldg(ep + j * 4);                 // pre-shifted (src*8)
                int4 r = __ldg(gsub + s);
                if (j & 1) {
                    o0 = __hadd2(o0, *(__half2*)&r.x);
                    o1 = __hadd2(o1, *(__half2*)&r.y);
                    o2 = __hadd2(o2, *(__half2*)&r.z);
                    o3 = __hadd2(o3, *(__half2*)&r.w);
                } else {
                    e0 = __hadd2(e0, *(__half2*)&r.x);
                    e1 = __hadd2(e1, *(__half2*)&r.y);
                    e2 = __hadd2(e2, *(__half2*)&r.z);
                    e3 = __hadd2(e3, *(__half2*)&r.w);
                }
            }
        }
    }

    __half2 acc0 = __hadd2(e0, o0);
    __half2 acc1 = __hadd2(e1, o1);
    __half2 acc2 = __hadd2(e2, o2);
    __half2 acc3 = __hadd2(e3, o3);

    // cross-group reduction in half2 (lane bits 3,4)
    #pragma unroll
    for (int m = 8; m <= 16; m <<= 1) {
        int t0 = __shfl_xor_sync(0xffffffffu, *(int*)&acc0, m);
        int t1 = __shfl_xor_sync(0xffffffffu, *(int*)&acc1, m);
        int t2 = __shfl_xor_sync(0xffffffffu, *(int*)&acc2, m);
        int t3 = __shfl_xor_sync(0xffffffffu, *(int*)&acc3, m);
        acc0 = __hadd2(acc0, *(__half2*)&t0);
        acc1 = __hadd2(acc1, *(__half2*)&t1);
        acc2 = __hadd2(acc2, *(__half2*)&t2);
        acc3 = __hadd2(acc3, *(__half2*)&t3);
    }

    float2 f0 = __half22float2(acc0);
    float2 f1 = __half22float2(acc1);
    float2 f2 = __half22float2(acc2);
    float2 f3 = __half22float2(acc3);
    float inn = d_inorm[n];
    float ex[8] = { f0.x * inn, f0.y * inn, f1.x * inn, f1.y * inn,
                    f2.x * inn, f2.y * inn, f3.x * inn, f3.y * inn };

    if (LAYER < 2) {
        if (grp == 0) {
            float onn = d_onorm[n];
            __half2 h0 = __floats2half2_rn(ex[0] * onn, ex[1] * onn);
            __half2 h1 = __floats2half2_rn(ex[2] * onn, ex[3] * onn);
            __half2 h2 = __floats2half2_rn(ex[4] * onn, ex[5] * onn);
            __half2 h3 = __floats2half2_rn(ex[6] * onn, ex[7] * onn);
            int4 r;
            r.x = *(int*)&h0; r.y = *(int*)&h1; r.z = *(int*)&h2; r.w = *(int*)&h3;
            gout4[n * 8 + sub] = r;
        }
    } else {
        // final combine: out = emb + oinv*(g1/2 + g2/3) + ex/4
        if (grp < 2) {
            const float4* erow = (n < USER_NUM)
                ? ((const float4*)user + (size_t)n * 16)
                : ((const float4*)item + (size_t)(n - USER_NUM) * 16);
            int q = sub * 2 + grp;      // float4 index 0..15
            int o = grp * 4;
            float oinv = d_oinv[n];
            float c1 = oinv * (1.0f / 2.0f);
            float c2 = oinv * (1.0f / 3.0f);

            const __half2* g1row = d_gB + n * 32 + q * 2;
            const __half2* g2row = d_gC + n * 32 + q * 2;
            float2 a1 = __half22float2(g1row[0]);
            float2 b1 = __half22float2(g1row[1]);
            float2 a2 = __half22float2(g2row[0]);
            float2 b2 = __half22float2(g2row[1]);

            float4 ev = __ldg(erow + q);
            float4 ov;
            ov.x = ev.x + a1.x * c1 + a2.x * c2 + ex[o + 0] * 0.25f;
            ov.y = ev.y + a1.y * c1 + a2.y * c2 + ex[o + 1] * 0.25f;
            ov.z = ev.z + b1.x * c1 + b2.x * c2 + ex[o + 2] * 0.25f;
            ov.w = ev.w + b1.y * c1 + b2.y * c2 + ex[o + 3] * 0.25f;
            ((float4*)(out + (size_t)n * HD))[q] = ov;
        }
        if (lane == 0) {               // restore initial state for next replay
            d_deg_out[n] = 0;
            d_deg_in[n] = 0;
        }
    }
}

extern "C" void kernel_launch(void* const* d_in, const int* in_sizes, int n_in,
                              void* d_out, int out_size) {
    const float* user = (const float*)d_in[0];
    const float* item = (const float*)d_in[1];
    const int4*  src4 = (const int4*)d_in[2];
    const int4*  dst4 = (const int4*)d_in[3];
    float*       out  = (float*)d_out;

    const int EV_BLOCKS  = (N_EDGES / 4 + 255) / 256;          // 3907
    const int MRG_BLOCKS = (N_NODES * (HD / 4) + 255) / 256;   // 9375
    const int AGG_BLOCKS = (N_NODES * 32) / 256;               // 18750, exact

    k_hist<<<EV_BLOCKS, 256>>>(src4, dst4);                          // 1
    k_scanA<<<SCAN_NB, SCAN_BLK>>>();                                // 2
    k_scanC<<<SCAN_NB, SCAN_BLK>>>();                                // 3
    k_scatter_init<<<MRG_BLOCKS, 256>>>(src4, dst4, user, item);     // 4 <-- profiled
    k_aggh<0><<<AGG_BLOCKS, 256>>>(user, item, out);                 // 5: g0 -> g1
    k_aggh<1><<<AGG_BLOCKS, 256>>>(user, item, out);                 // 6: g1 -> g2
    k_aggh<2><<<AGG_BLOCKS, 256>>>(user, item, out);                 // 7: final combine
}